// round 15
// baseline (speedup 1.0000x reference)
#include <cuda_runtime.h>
#include <cstdint>

#define HH 2048
#define WW 2048
#define NPIX (HH*WW)

// Output tile: 56 rows x 128 cols, 512 threads. Grid = 16 x 37 = 592 blocks
// = 148 SMs * 4 blocks -> exactly one perfectly balanced wave, 64 warps/SM.
#define TROWS 56
#define TCOLS 128
#define GX (WW / TCOLS)                 // 16
#define GY ((HH + TROWS - 1) / TROWS)   // 37
// SMEM box: 58 rows x 130 cols used, pitch 132.
#define SROWS 58
#define SPITCH 132

// Scratch (allocation-free rule: __device__ globals)
__device__ float g_bufA[NPIX];
__device__ float g_bufB[NPIX];
__device__ float g_good[NPIX];

// ---------------- Threefry-2x32 (exact JAX semantics) ----------------
// SHF-based rotate (alu pipe)
__device__ __forceinline__ uint32_t rotl32(uint32_t x, int r) {
    return __funnelshift_l(x, x, r);
}

// Add routed to the FMA pipe: mad.lo.u32 with an opaque multiplier (==1 at
// runtime, passed as kernel arg so ptxas cannot fold it to IADD3).
// Exact mod-2^32 => bit-identical to a plain add.
__device__ __forceinline__ uint32_t addf(uint32_t a, uint32_t b, uint32_t one) {
    uint32_t r;
    asm("mad.lo.u32 %0, %1, %2, %3;" : "=r"(r) : "r"(a), "r"(one), "r"(b));
    return r;
}

// IMAD-based rotate (fma pipe): x ROTL r == lo(x * 2^r) + hi(x * 2^r)
// (the two halves have disjoint bit positions, so OR == ADD; exact).
__device__ __forceinline__ uint32_t rotl_imad(uint32_t x, int r, uint32_t one) {
    uint64_t t;
    asm("mul.wide.u32 %0, %1, %2;" : "=l"(t) : "r"(x), "r"(1u << r));
    return addf((uint32_t)t, (uint32_t)(t >> 32), one);
}

// Mantissa pack on the fma pipe: hi32(bits*2^23 + 0x3f800000*2^32)
// == (bits >> 9) | 0x3f800000 exactly (no carry into the hi word).
__device__ __forceinline__ float mantissa_f(uint32_t bits) {
    uint64_t t;
    asm("mad.wide.u32 %0, %1, %2, %3;"
        : "=l"(t) : "r"(bits), "r"(0x800000u), "l"(0x3f80000000000000ull));
    return __uint_as_float((uint32_t)(t >> 32));
}

__device__ __forceinline__ void tf2x32(uint32_t k0, uint32_t k1,
                                       uint32_t x1in, uint32_t one,
                                       uint32_t& o0, uint32_t& o1) {
    // counter = (0, j): x0 starts as k0, x1 = j + k1
    uint32_t k2 = k0 ^ k1 ^ 0x1BD11BDAu;
    uint32_t x0 = k0;
    uint32_t x1 = addf(x1in, k1, one);
    // Pipe mix probe: 14 rotates via SHF (alu), 6 via IMAD-wide (fma).
#define TF_R(rot) \
    x0 = addf(x0, x1, one); x1 = rotl32(x1, rot) ^ x0;
#define TF_RI(rot) \
    x0 = addf(x0, x1, one); x1 = rotl_imad(x1, rot, one) ^ x0;
#define TF_G1(a,b,c,d) TF_R(a) TF_R(b) TF_R(c) TF_RI(d)
#define TF_G2(a,b,c,d) TF_R(a) TF_RI(b) TF_R(c) TF_RI(d)
#define TF_G0(a,b,c,d) TF_R(a) TF_R(b) TF_R(c) TF_R(d)
    TF_G1(13,15,26,6)   x0 = addf(x0, k1, one); x1 = addf(x1, k2 + 1u, one);
    TF_G2(17,29,16,24)  x0 = addf(x0, k2, one); x1 = addf(x1, k0 + 2u, one);
    TF_G1(13,15,26,6)   x0 = addf(x0, k0, one); x1 = addf(x1, k1 + 3u, one);
    TF_G2(17,29,16,24)  x0 = addf(x0, k1, one); x1 = addf(x1, k2 + 4u, one);
    TF_G0(13,15,26,6)   x0 = addf(x0, k2, one); x1 = addf(x1, k0 + 5u, one);
#undef TF_G0
#undef TF_G2
#undef TF_G1
#undef TF_RI
#undef TF_R
    o0 = x0; o1 = x1;
}

// Host copy for key derivation (split of key(1) into 100 keys)
static inline uint32_t h_rotl32(uint32_t x, int r) { return (x << r) | (x >> (32 - r)); }
static void h_tf2x32(uint32_t k0, uint32_t k1, uint32_t x0, uint32_t x1,
                     uint32_t& o0, uint32_t& o1) {
    uint32_t k2 = k0 ^ k1 ^ 0x1BD11BDAu;
    x0 += k0; x1 += k1;
#define TF_R4(a,b,c,d) \
    x0 += x1; x1 = h_rotl32(x1,a); x1 ^= x0; \
    x0 += x1; x1 = h_rotl32(x1,b); x1 ^= x0; \
    x0 += x1; x1 = h_rotl32(x1,c); x1 ^= x0; \
    x0 += x1; x1 = h_rotl32(x1,d); x1 ^= x0;
    TF_R4(13,15,26,6)   x0 += k1; x1 += k2 + 1u;
    TF_R4(17,29,16,24)  x0 += k2; x1 += k0 + 2u;
    TF_R4(13,15,26,6)   x0 += k0; x1 += k1 + 3u;
    TF_R4(17,29,16,24)  x0 += k1; x1 += k2 + 4u;
    TF_R4(13,15,26,6)   x0 += k2; x1 += k0 + 5u;
#undef TF_R4
    o0 = x0; o1 = x1;
}

// ---------------- Kernels ----------------
__global__ __launch_bounds__(256) void init_kernel(
    const float* __restrict__ seed, const float* __restrict__ hab,
    const float* __restrict__ ter) {
    int i = blockIdx.x * 256 + threadIdx.x;
    g_bufA[i] = seed[i] * hab[i];
    g_good[i] = fmaxf(hab[i], ter[i]);
}

// One spread step: xs = src * (0.9 + 0.1*U(key, idx)); dst = max(maxpool3x3(xs)*good, src)
// FINAL step additionally multiplies by habitat (fused epilogue).
template <bool FINAL>
__global__ __launch_bounds__(512, 4) void step_kernel(
    const float* __restrict__ src, float* __restrict__ dst,
    const float* __restrict__ good, const float* __restrict__ hab,
    uint32_t k0, uint32_t k1, uint32_t one) {
    __shared__ float xs[SROWS][SPITCH];

    const int r0 = blockIdx.y * TROWS;   // output tile origin
    const int c0 = blockIdx.x * TCOLS;
    const int tid = threadIdx.x;

    // ---- Phase 1a: halo columns (2 x 58 pixels) on warps 12-15 ----
    // Those warps belong to the lr==3 strip, which does only 14 sweep
    // ciphers (no tail iteration) -> halo balances them to 15, matching
    // the lr==0/1 strips. Max ciphers per warp drops 16 -> 15.
    // xs col 0 = global col c0-1, xs col 129 = global col c0+128.
    {
        int t2 = tid - 384;
        bool left  = (t2 >= 0 && t2 < 58);
        bool right = (t2 >= 64 && t2 < 122);
        if (left || right) {
            int rr  = left ? t2 : t2 - 64;
            int row = r0 - 1 + rr;
            int col = left ? c0 - 1 : c0 + TCOLS;
            uint32_t j = (uint32_t)((row << 11) + col);
            uint32_t o0, o1;
            tf2x32(k0, k1, j, one, o0, o1);
            float f = mantissa_f(o0 ^ o1);             // [1,2)
            float v = 0.0f;  // SAME padding: data >= 0, so 0 == -inf here
            if ((unsigned)row < HH && (unsigned)col < WW)
                v = __ldg(&src[j]) * fmaf(0.1f, f, 0.8f);
            xs[rr][left ? 0 : 129] = v;
        }
    }

    // ---- Phase 1b: tile proper (58 x 128) — shift/mask indexing only ----
    // Thread (lr, lc): rows lr+4i; col c0+lc always valid. Across unrolled
    // iterations row += 4 / j += 8192 are immediates folding into the
    // cipher's first add and the LDG/STS offsets.
    const int lr = tid >> 7;             // 0..3
    const int lc = tid & 127;
    const int row0 = r0 - 1 + lr;
    const uint32_t jbase = (uint32_t)((row0 << 11) + c0 + lc);
    #pragma unroll
    for (int i = 0; i < 14; i++) {
        int row = row0 + 4 * i;
        uint32_t j = jbase + (uint32_t)(8192 * i);
        uint32_t o0, o1;
        tf2x32(k0, k1, j, one, o0, o1);
        float f = mantissa_f(o0 ^ o1);                 // [1,2)
        // 0.9 + 0.1*(f-1) folded to fma(0.1, f, 0.8)  (diff O(1e-7))
        float v = 0.0f;
        if ((unsigned)row < HH)          // only row guard needed
            v = __ldg(&src[j]) * fmaf(0.1f, f, 0.8f);
        xs[lr + 4 * i][lc + 1] = v;
    }
    // Iteration 14: only rows 56,57 (lr < 2) are real — skip padding work.
    if (lr < 2) {
        int row = row0 + 56;
        uint32_t j = jbase + (uint32_t)(8192 * 14);
        uint32_t o0, o1;
        tf2x32(k0, k1, j, one, o0, o1);
        float f = mantissa_f(o0 ^ o1);
        float v = 0.0f;
        if ((unsigned)row < HH)
            v = __ldg(&src[j]) * fmaf(0.1f, f, 0.8f);
        xs[lr + 56][lc + 1] = v;
    }
    __syncthreads();

    // ---- Phase 2: separable 3x3 max, rolling vertical window ----
    // 512 threads = 128 cols x 4 row-strips of 14. All 128 cols valid
    // (tile width divides W) -> only a row guard needed.
    const int oc = tid & 127;          // output col; smem cols oc..oc+2
    const int rs = (tid >> 7) * 14;    // output-row base within tile

    float h0 = fmaxf(fmaxf(xs[rs    ][oc], xs[rs    ][oc+1]), xs[rs    ][oc+2]);
    float h1 = fmaxf(fmaxf(xs[rs + 1][oc], xs[rs + 1][oc+1]), xs[rs + 1][oc+2]);
    #pragma unroll
    for (int i = 0; i < 14; i++) {
        int sr = rs + i + 2;
        float h2 = fmaxf(fmaxf(xs[sr][oc], xs[sr][oc+1]), xs[sr][oc+2]);
        float m = fmaxf(fmaxf(h0, h1), h2);
        int r = r0 + rs + i;
        if (r < HH) {
            int g = (r << 11) + (c0 + oc);
            float xc = __ldg(&src[g]);
            float res = fmaxf(m * __ldg(&good[g]), xc);
            if (FINAL) res *= __ldg(&hab[g]);
            dst[g] = res;
        }
        h0 = h1; h1 = h2;
    }
}

// ---------------- Launch ----------------
extern "C" void kernel_launch(void* const* d_in, const int* in_sizes, int n_in,
                              void* d_out, int out_size) {
    (void)in_sizes; (void)n_in; (void)out_size;
    const float* seedp = (const float*)d_in[0];
    const float* habp  = (const float*)d_in[1];
    const float* terp  = (const float*)d_in[2];
    float* outp = (float*)d_out;

    float *bufA = nullptr, *bufB = nullptr, *goodp = nullptr;
    cudaGetSymbolAddress((void**)&bufA, g_bufA);
    cudaGetSymbolAddress((void**)&bufB, g_bufB);
    cudaGetSymbolAddress((void**)&goodp, g_good);

    init_kernel<<<NPIX / 256, 256>>>(seedp, habp, terp);

    // keys = jax.random.split(jax.random.key(1), 100), partitionable:
    // key_t = threefry2x32((0,1), (0,t))
    uint32_t keys[100][2];
    for (uint32_t t = 0; t < 100; t++)
        h_tf2x32(0u, 1u, 0u, t, keys[t][0], keys[t][1]);

    const uint32_t one = 1u;  // opaque to ptxas: keeps mad.lo as IMAD (fma pipe)

    dim3 grid(GX, GY);  // 16 x 37 = 592 blocks = 148 SMs * 4  (single wave)
    const float* s = bufA;
    float* d = bufB;
    for (int t = 0; t < 99; t++) {
        step_kernel<false><<<grid, 512>>>(s, d, goodp, habp,
                                          keys[t][0], keys[t][1], one);
        const float* tmp = d;
        d = (float*)s;
        s = tmp;
    }
    // Final step: fused * habitat epilogue, writes directly to d_out.
    step_kernel<true><<<grid, 512>>>(s, outp, goodp, habp,
                                     keys[99][0], keys[99][1], one);
}

// round 16
// speedup vs baseline: 1.0461x; 1.0461x over previous
#include <cuda_runtime.h>
#include <cstdint>

#define HH 2048
#define WW 2048
#define NPIX (HH*WW)

// Output tile: 56 rows x 128 cols, 512 threads. Grid = 16 x 37 = 592 blocks
// = 148 SMs * 4 blocks -> exactly one perfectly balanced wave, 64 warps/SM.
#define TROWS 56
#define TCOLS 128
#define GX (WW / TCOLS)                 // 16
#define GY ((HH + TROWS - 1) / TROWS)   // 37
// SMEM box: 58 rows x 130 cols used, pitch 132.
#define SROWS 58
#define SPITCH 132

// Scratch (allocation-free rule: __device__ globals)
__device__ float g_bufA[NPIX];
__device__ float g_bufB[NPIX];
__device__ float g_good[NPIX];

// ---------------- Threefry-2x32 (exact JAX semantics) ----------------
// SHF-based rotate (alu pipe)
__device__ __forceinline__ uint32_t rotl32(uint32_t x, int r) {
    return __funnelshift_l(x, x, r);
}

// Add routed to the FMA pipe: mad.lo.u32 with an opaque multiplier (==1 at
// runtime, passed as kernel arg so ptxas cannot fold it to IADD3).
// Exact mod-2^32 => bit-identical to a plain add.
__device__ __forceinline__ uint32_t addf(uint32_t a, uint32_t b, uint32_t one) {
    uint32_t r;
    asm("mad.lo.u32 %0, %1, %2, %3;" : "=r"(r) : "r"(a), "r"(one), "r"(b));
    return r;
}

// IMAD-based rotate (fma pipe): x ROTL r == lo(x * 2^r) + hi(x * 2^r)
// (the two halves have disjoint bit positions, so OR == ADD; exact).
__device__ __forceinline__ uint32_t rotl_imad(uint32_t x, int r, uint32_t one) {
    uint64_t t;
    asm("mul.wide.u32 %0, %1, %2;" : "=l"(t) : "r"(x), "r"(1u << r));
    return addf((uint32_t)t, (uint32_t)(t >> 32), one);
}

// Mantissa pack on the fma pipe: hi32(bits*2^23 + 0x3f800000*2^32)
// == (bits >> 9) | 0x3f800000 exactly (no carry into the hi word).
__device__ __forceinline__ float mantissa_f(uint32_t bits) {
    uint64_t t;
    asm("mad.wide.u32 %0, %1, %2, %3;"
        : "=l"(t) : "r"(bits), "r"(0x800000u), "l"(0x3f80000000000000ull));
    return __uint_as_float((uint32_t)(t >> 32));
}

__device__ __forceinline__ void tf2x32(uint32_t k0, uint32_t k1,
                                       uint32_t x1in, uint32_t one,
                                       uint32_t& o0, uint32_t& o1) {
    // counter = (0, j): x0 starts as k0, x1 = j + k1
    uint32_t k2 = k0 ^ k1 ^ 0x1BD11BDAu;
    uint32_t x0 = k0;
    uint32_t x1 = addf(x1in, k1, one);
    // Measured-optimal pipe mix (R6/R14): 16 rotates via SHF (alu), 4 via
    // IMAD-wide (fma). 6+ conversions over-serialize (R8, R15).
#define TF_R(rot) \
    x0 = addf(x0, x1, one); x1 = rotl32(x1, rot) ^ x0;
#define TF_RI(rot) \
    x0 = addf(x0, x1, one); x1 = rotl_imad(x1, rot, one) ^ x0;
#define TF_G(a,b,c,d) TF_R(a) TF_R(b) TF_R(c) TF_RI(d)
#define TF_G5(a,b,c,d) TF_R(a) TF_R(b) TF_R(c) TF_R(d)
    TF_G(13,15,26,6)    x0 = addf(x0, k1, one); x1 = addf(x1, k2 + 1u, one);
    TF_G(17,29,16,24)   x0 = addf(x0, k2, one); x1 = addf(x1, k0 + 2u, one);
    TF_G(13,15,26,6)    x0 = addf(x0, k0, one); x1 = addf(x1, k1 + 3u, one);
    TF_G(17,29,16,24)   x0 = addf(x0, k1, one); x1 = addf(x1, k2 + 4u, one);
    TF_G5(13,15,26,6)   x0 = addf(x0, k2, one); x1 = addf(x1, k0 + 5u, one);
#undef TF_G5
#undef TF_G
#undef TF_RI
#undef TF_R
    o0 = x0; o1 = x1;
}

// Host copy for key derivation (split of key(1) into 100 keys)
static inline uint32_t h_rotl32(uint32_t x, int r) { return (x << r) | (x >> (32 - r)); }
static void h_tf2x32(uint32_t k0, uint32_t k1, uint32_t x0, uint32_t x1,
                     uint32_t& o0, uint32_t& o1) {
    uint32_t k2 = k0 ^ k1 ^ 0x1BD11BDAu;
    x0 += k0; x1 += k1;
#define TF_R4(a,b,c,d) \
    x0 += x1; x1 = h_rotl32(x1,a); x1 ^= x0; \
    x0 += x1; x1 = h_rotl32(x1,b); x1 ^= x0; \
    x0 += x1; x1 = h_rotl32(x1,c); x1 ^= x0; \
    x0 += x1; x1 = h_rotl32(x1,d); x1 ^= x0;
    TF_R4(13,15,26,6)   x0 += k1; x1 += k2 + 1u;
    TF_R4(17,29,16,24)  x0 += k2; x1 += k0 + 2u;
    TF_R4(13,15,26,6)   x0 += k0; x1 += k1 + 3u;
    TF_R4(17,29,16,24)  x0 += k1; x1 += k2 + 4u;
    TF_R4(13,15,26,6)   x0 += k2; x1 += k0 + 5u;
#undef TF_R4
    o0 = x0; o1 = x1;
}

// ---------------- Kernels ----------------
__global__ __launch_bounds__(256) void init_kernel(
    const float* __restrict__ seed, const float* __restrict__ hab,
    const float* __restrict__ ter) {
    int i = blockIdx.x * 256 + threadIdx.x;
    g_bufA[i] = seed[i] * hab[i];
    g_good[i] = fmaxf(hab[i], ter[i]);
}

// One spread step: xs = src * (0.9 + 0.1*U(key, idx)); dst = max(maxpool3x3(xs)*good, src)
// FINAL step additionally multiplies by habitat (fused epilogue).
template <bool FINAL>
__global__ __launch_bounds__(512, 4) void step_kernel(
    const float* __restrict__ src, float* __restrict__ dst,
    const float* __restrict__ good, const float* __restrict__ hab,
    uint32_t k0, uint32_t k1, uint32_t one) {
    __shared__ float xs[SROWS][SPITCH];

    const int r0 = blockIdx.y * TROWS;   // output tile origin
    const int c0 = blockIdx.x * TCOLS;
    const int tid = threadIdx.x;

    // ---- Phase 1a: halo columns (2 x 58 pixels) on warps 12-15 ----
    // Those warps belong to the lr==3 strip, which does only 14 sweep
    // ciphers (no tail iteration) -> halo balances them to 15, matching
    // the lr==0/1 strips. Max ciphers per warp drops 16 -> 15.
    // xs col 0 = global col c0-1, xs col 129 = global col c0+128.
    {
        int t2 = tid - 384;
        bool left  = (t2 >= 0 && t2 < 58);
        bool right = (t2 >= 64 && t2 < 122);
        if (left || right) {
            int rr  = left ? t2 : t2 - 64;
            int row = r0 - 1 + rr;
            int col = left ? c0 - 1 : c0 + TCOLS;
            uint32_t j = (uint32_t)((row << 11) + col);
            uint32_t o0, o1;
            tf2x32(k0, k1, j, one, o0, o1);
            float f = mantissa_f(o0 ^ o1);             // [1,2)
            float v = 0.0f;  // SAME padding: data >= 0, so 0 == -inf here
            if ((unsigned)row < HH && (unsigned)col < WW)
                v = __ldg(&src[j]) * fmaf(0.1f, f, 0.8f);
            xs[rr][left ? 0 : 129] = v;
        }
    }

    // ---- Phase 1b: tile proper (58 x 128) — shift/mask indexing only ----
    // Thread (lr, lc): rows lr+4i; col c0+lc always valid. Across unrolled
    // iterations row += 4 / j += 8192 are immediates folding into the
    // cipher's first add and the LDG/STS offsets.
    const int lr = tid >> 7;             // 0..3
    const int lc = tid & 127;
    const int row0 = r0 - 1 + lr;
    const uint32_t jbase = (uint32_t)((row0 << 11) + c0 + lc);
    #pragma unroll
    for (int i = 0; i < 14; i++) {
        int row = row0 + 4 * i;
        uint32_t j = jbase + (uint32_t)(8192 * i);
        uint32_t o0, o1;
        tf2x32(k0, k1, j, one, o0, o1);
        float f = mantissa_f(o0 ^ o1);                 // [1,2)
        // 0.9 + 0.1*(f-1) folded to fma(0.1, f, 0.8)  (diff O(1e-7))
        float v = 0.0f;
        if ((unsigned)row < HH)          // only row guard needed
            v = __ldg(&src[j]) * fmaf(0.1f, f, 0.8f);
        xs[lr + 4 * i][lc + 1] = v;
    }
    // Iteration 14: only rows 56,57 (lr < 2) are real — skip padding work.
    if (lr < 2) {
        int row = row0 + 56;
        uint32_t j = jbase + (uint32_t)(8192 * 14);
        uint32_t o0, o1;
        tf2x32(k0, k1, j, one, o0, o1);
        float f = mantissa_f(o0 ^ o1);
        float v = 0.0f;
        if ((unsigned)row < HH)
            v = __ldg(&src[j]) * fmaf(0.1f, f, 0.8f);
        xs[lr + 56][lc + 1] = v;
    }
    __syncthreads();

    // ---- Phase 2: separable 3x3 max, rolling vertical window ----
    // 512 threads = 128 cols x 4 row-strips of 14. All 128 cols valid
    // (tile width divides W) -> only a row guard needed.
    const int oc = tid & 127;          // output col; smem cols oc..oc+2
    const int rs = (tid >> 7) * 14;    // output-row base within tile

    float h0 = fmaxf(fmaxf(xs[rs    ][oc], xs[rs    ][oc+1]), xs[rs    ][oc+2]);
    float h1 = fmaxf(fmaxf(xs[rs + 1][oc], xs[rs + 1][oc+1]), xs[rs + 1][oc+2]);
    #pragma unroll
    for (int i = 0; i < 14; i++) {
        int sr = rs + i + 2;
        float h2 = fmaxf(fmaxf(xs[sr][oc], xs[sr][oc+1]), xs[sr][oc+2]);
        float m = fmaxf(fmaxf(h0, h1), h2);
        int r = r0 + rs + i;
        if (r < HH) {
            int g = (r << 11) + (c0 + oc);
            float xc = __ldg(&src[g]);
            float res = fmaxf(m * __ldg(&good[g]), xc);
            if (FINAL) res *= __ldg(&hab[g]);
            dst[g] = res;
        }
        h0 = h1; h1 = h2;
    }
}

// ---------------- Launch ----------------
extern "C" void kernel_launch(void* const* d_in, const int* in_sizes, int n_in,
                              void* d_out, int out_size) {
    (void)in_sizes; (void)n_in; (void)out_size;
    const float* seedp = (const float*)d_in[0];
    const float* habp  = (const float*)d_in[1];
    const float* terp  = (const float*)d_in[2];
    float* outp = (float*)d_out;

    float *bufA = nullptr, *bufB = nullptr, *goodp = nullptr;
    cudaGetSymbolAddress((void**)&bufA, g_bufA);
    cudaGetSymbolAddress((void**)&bufB, g_bufB);
    cudaGetSymbolAddress((void**)&goodp, g_good);

    init_kernel<<<NPIX / 256, 256>>>(seedp, habp, terp);

    // keys = jax.random.split(jax.random.key(1), 100), partitionable:
    // key_t = threefry2x32((0,1), (0,t))
    uint32_t keys[100][2];
    for (uint32_t t = 0; t < 100; t++)
        h_tf2x32(0u, 1u, 0u, t, keys[t][0], keys[t][1]);

    const uint32_t one = 1u;  // opaque to ptxas: keeps mad.lo as IMAD (fma pipe)

    dim3 grid(GX, GY);  // 16 x 37 = 592 blocks = 148 SMs * 4  (single wave)
    const float* s = bufA;
    float* d = bufB;
    for (int t = 0; t < 99; t++) {
        step_kernel<false><<<grid, 512>>>(s, d, goodp, habp,
                                          keys[t][0], keys[t][1], one);
        const float* tmp = d;
        d = (float*)s;
        s = tmp;
    }
    // Final step: fused * habitat epilogue, writes directly to d_out.
    step_kernel<true><<<grid, 512>>>(s, outp, goodp, habp,
                                     keys[99][0], keys[99][1], one);
}

// round 17
// speedup vs baseline: 1.0617x; 1.0149x over previous
#include <cuda_runtime.h>
#include <cstdint>

#define HH 2048
#define WW 2048
#define NPIX (HH*WW)

// Output tile: 56 rows x 128 cols, 512 threads. Grid = 16 x 37 = 592 blocks
// = 148 SMs * 4 blocks -> exactly one perfectly balanced wave, 64 warps/SM.
#define TROWS 56
#define TCOLS 128
#define GX (WW / TCOLS)                 // 16
#define GY ((HH + TROWS - 1) / TROWS)   // 37
// SMEM box: 58 rows x 130 cols used, pitch 132 (528B rows, 16B aligned).
#define SROWS 58
#define SPITCH 132

// Scratch (allocation-free rule: __device__ globals)
__device__ float g_bufA[NPIX];
__device__ float g_bufB[NPIX];
__device__ float g_good[NPIX];

// ---------------- Threefry-2x32 (exact JAX semantics) ----------------
// SHF-based rotate (alu pipe)
__device__ __forceinline__ uint32_t rotl32(uint32_t x, int r) {
    return __funnelshift_l(x, x, r);
}

// Add routed to the FMA pipe: mad.lo.u32 with an opaque multiplier (==1 at
// runtime, passed as kernel arg so ptxas cannot fold it to IADD3).
// Exact mod-2^32 => bit-identical to a plain add.
__device__ __forceinline__ uint32_t addf(uint32_t a, uint32_t b, uint32_t one) {
    uint32_t r;
    asm("mad.lo.u32 %0, %1, %2, %3;" : "=r"(r) : "r"(a), "r"(one), "r"(b));
    return r;
}

// IMAD-based rotate (fma pipe): x ROTL r == lo(x * 2^r) + hi(x * 2^r)
// (the two halves have disjoint bit positions, so OR == ADD; exact).
__device__ __forceinline__ uint32_t rotl_imad(uint32_t x, int r, uint32_t one) {
    uint64_t t;
    asm("mul.wide.u32 %0, %1, %2;" : "=l"(t) : "r"(x), "r"(1u << r));
    return addf((uint32_t)t, (uint32_t)(t >> 32), one);
}

// Mantissa pack on the fma pipe: hi32(bits*2^23 + 0x3f800000*2^32)
// == (bits >> 9) | 0x3f800000 exactly (no carry into the hi word).
__device__ __forceinline__ float mantissa_f(uint32_t bits) {
    uint64_t t;
    asm("mad.wide.u32 %0, %1, %2, %3;"
        : "=l"(t) : "r"(bits), "r"(0x800000u), "l"(0x3f80000000000000ull));
    return __uint_as_float((uint32_t)(t >> 32));
}

__device__ __forceinline__ void tf2x32(uint32_t k0, uint32_t k1,
                                       uint32_t x1in, uint32_t one,
                                       uint32_t& o0, uint32_t& o1) {
    // counter = (0, j): x0 starts as k0, x1 = j + k1
    uint32_t k2 = k0 ^ k1 ^ 0x1BD11BDAu;
    uint32_t x0 = k0;
    uint32_t x1 = addf(x1in, k1, one);
    // Measured-optimal pipe mix (R6/R14): 16 rotates via SHF (alu), 4 via
    // IMAD-wide (fma). 6+ conversions over-serialize (R8, R15).
#define TF_R(rot) \
    x0 = addf(x0, x1, one); x1 = rotl32(x1, rot) ^ x0;
#define TF_RI(rot) \
    x0 = addf(x0, x1, one); x1 = rotl_imad(x1, rot, one) ^ x0;
#define TF_G(a,b,c,d) TF_R(a) TF_R(b) TF_R(c) TF_RI(d)
#define TF_G5(a,b,c,d) TF_R(a) TF_R(b) TF_R(c) TF_R(d)
    TF_G(13,15,26,6)    x0 = addf(x0, k1, one); x1 = addf(x1, k2 + 1u, one);
    TF_G(17,29,16,24)   x0 = addf(x0, k2, one); x1 = addf(x1, k0 + 2u, one);
    TF_G(13,15,26,6)    x0 = addf(x0, k0, one); x1 = addf(x1, k1 + 3u, one);
    TF_G(17,29,16,24)   x0 = addf(x0, k1, one); x1 = addf(x1, k2 + 4u, one);
    TF_G5(13,15,26,6)   x0 = addf(x0, k2, one); x1 = addf(x1, k0 + 5u, one);
#undef TF_G5
#undef TF_G
#undef TF_RI
#undef TF_R
    o0 = x0; o1 = x1;
}

// Host copy for key derivation (split of key(1) into 100 keys)
static inline uint32_t h_rotl32(uint32_t x, int r) { return (x << r) | (x >> (32 - r)); }
static void h_tf2x32(uint32_t k0, uint32_t k1, uint32_t x0, uint32_t x1,
                     uint32_t& o0, uint32_t& o1) {
    uint32_t k2 = k0 ^ k1 ^ 0x1BD11BDAu;
    x0 += k0; x1 += k1;
#define TF_R4(a,b,c,d) \
    x0 += x1; x1 = h_rotl32(x1,a); x1 ^= x0; \
    x0 += x1; x1 = h_rotl32(x1,b); x1 ^= x0; \
    x0 += x1; x1 = h_rotl32(x1,c); x1 ^= x0; \
    x0 += x1; x1 = h_rotl32(x1,d); x1 ^= x0;
    TF_R4(13,15,26,6)   x0 += k1; x1 += k2 + 1u;
    TF_R4(17,29,16,24)  x0 += k2; x1 += k0 + 2u;
    TF_R4(13,15,26,6)   x0 += k0; x1 += k1 + 3u;
    TF_R4(17,29,16,24)  x0 += k1; x1 += k2 + 4u;
    TF_R4(13,15,26,6)   x0 += k2; x1 += k0 + 5u;
#undef TF_R4
    o0 = x0; o1 = x1;
}

// ---------------- Kernels ----------------
__global__ __launch_bounds__(256) void init_kernel(
    const float* __restrict__ seed, const float* __restrict__ hab,
    const float* __restrict__ ter) {
    int i = blockIdx.x * 256 + threadIdx.x;
    g_bufA[i] = seed[i] * hab[i];
    g_good[i] = fmaxf(hab[i], ter[i]);
}

// One spread step: xs = src * (0.9 + 0.1*U(key, idx)); dst = max(maxpool3x3(xs)*good, src)
// FINAL step additionally multiplies by habitat (fused epilogue).
template <bool FINAL>
__global__ __launch_bounds__(512, 4) void step_kernel(
    const float* __restrict__ src, float* __restrict__ dst,
    const float* __restrict__ good, const float* __restrict__ hab,
    uint32_t k0, uint32_t k1, uint32_t one) {
    __shared__ float xs[SROWS][SPITCH];

    const int r0 = blockIdx.y * TROWS;   // output tile origin
    const int c0 = blockIdx.x * TCOLS;
    const int tid = threadIdx.x;

    // ---- Phase 1a: halo columns (2 x 58 pixels) on warps 12-15 ----
    // Those warps belong to the lr==3 strip, which does only 14 sweep
    // ciphers (no tail iteration) -> halo balances them to 15 ciphers,
    // matching the lr==0/1 strips (R16: verified win).
    // xs col 0 = global col c0-1, xs col 129 = global col c0+128.
    {
        int t2 = tid - 384;
        bool left  = (t2 >= 0 && t2 < 58);
        bool right = (t2 >= 64 && t2 < 122);
        if (left || right) {
            int rr  = left ? t2 : t2 - 64;
            int row = r0 - 1 + rr;
            int col = left ? c0 - 1 : c0 + TCOLS;
            uint32_t j = (uint32_t)((row << 11) + col);
            uint32_t o0, o1;
            tf2x32(k0, k1, j, one, o0, o1);
            float f = mantissa_f(o0 ^ o1);             // [1,2)
            float v = 0.0f;  // SAME padding: data >= 0, so 0 == -inf here
            if ((unsigned)row < HH && (unsigned)col < WW)
                v = __ldg(&src[j]) * fmaf(0.1f, f, 0.8f);
            xs[rr][left ? 0 : 129] = v;
        }
    }

    // ---- Phase 1b: tile proper (58 x 128) — shift/mask indexing only ----
    const int lr = tid >> 7;             // 0..3
    const int lc = tid & 127;
    const int row0 = r0 - 1 + lr;
    const uint32_t jbase = (uint32_t)((row0 << 11) + c0 + lc);
    #pragma unroll
    for (int i = 0; i < 14; i++) {
        int row = row0 + 4 * i;
        uint32_t j = jbase + (uint32_t)(8192 * i);
        uint32_t o0, o1;
        tf2x32(k0, k1, j, one, o0, o1);
        float f = mantissa_f(o0 ^ o1);                 // [1,2)
        // 0.9 + 0.1*(f-1) folded to fma(0.1, f, 0.8)  (diff O(1e-7))
        float v = 0.0f;
        if ((unsigned)row < HH)          // only row guard needed
            v = __ldg(&src[j]) * fmaf(0.1f, f, 0.8f);
        xs[lr + 4 * i][lc + 1] = v;
    }
    // Iteration 14: only rows 56,57 (lr < 2) are real — skip padding work.
    if (lr < 2) {
        int row = row0 + 56;
        uint32_t j = jbase + (uint32_t)(8192 * 14);
        uint32_t o0, o1;
        tf2x32(k0, k1, j, one, o0, o1);
        float f = mantissa_f(o0 ^ o1);
        float v = 0.0f;
        if ((unsigned)row < HH)
            v = __ldg(&src[j]) * fmaf(0.1f, f, 0.8f);
        xs[lr + 56][lc + 1] = v;
    }
    __syncthreads();

    // ---- Phase 2: separable 3x3 max, 2 output cols per thread ----
    // 512 threads = 64 col-pairs x 8 row-strips of 7. Per 2 outputs per
    // row: one pair of LDS.64 (4 consecutive floats), 3 shared-middle fmax
    // for the two horizontal maxes, vectorized float2 LDG/STG epilogue.
    const int cp = (tid & 63) * 2;     // output col-pair base (even)
    const int rs = (tid >> 6) * 7;     // output-row base within tile

    float2 a, b, t01;
#define LOAD4(ROW) \
    a = *(const float2*)&xs[ROW][cp]; \
    b = *(const float2*)&xs[ROW][cp + 2];
#define HPAIR(ha, hb) { \
    float tm = fmaxf(a.y, b.x); \
    ha = fmaxf(a.x, tm); hb = fmaxf(tm, b.y); }

    float h0a, h0b, h1a, h1b;
    LOAD4(rs)     HPAIR(h0a, h0b)
    LOAD4(rs + 1) HPAIR(h1a, h1b)
    #pragma unroll
    for (int i = 0; i < 7; i++) {
        float h2a, h2b;
        LOAD4(rs + i + 2) HPAIR(h2a, h2b)
        float ma = fmaxf(fmaxf(h0a, h1a), h2a);
        float mb = fmaxf(fmaxf(h0b, h1b), h2b);
        int r = r0 + rs + i;
        if (r < HH) {
            int g = (r << 11) + (c0 + cp);
            float2 xc = __ldg((const float2*)&src[g]);
            float2 gd = __ldg((const float2*)&good[g]);
            float2 res;
            res.x = fmaxf(ma * gd.x, xc.x);
            res.y = fmaxf(mb * gd.y, xc.y);
            if (FINAL) {
                float2 hb2 = __ldg((const float2*)&hab[g]);
                res.x *= hb2.x; res.y *= hb2.y;
            }
            *(float2*)&dst[g] = res;
        }
        h0a = h1a; h0b = h1b; h1a = h2a; h1b = h2b;
        (void)t01;
    }
#undef HPAIR
#undef LOAD4
}

// ---------------- Launch ----------------
extern "C" void kernel_launch(void* const* d_in, const int* in_sizes, int n_in,
                              void* d_out, int out_size) {
    (void)in_sizes; (void)n_in; (void)out_size;
    const float* seedp = (const float*)d_in[0];
    const float* habp  = (const float*)d_in[1];
    const float* terp  = (const float*)d_in[2];
    float* outp = (float*)d_out;

    float *bufA = nullptr, *bufB = nullptr, *goodp = nullptr;
    cudaGetSymbolAddress((void**)&bufA, g_bufA);
    cudaGetSymbolAddress((void**)&bufB, g_bufB);
    cudaGetSymbolAddress((void**)&goodp, g_good);

    init_kernel<<<NPIX / 256, 256>>>(seedp, habp, terp);

    // keys = jax.random.split(jax.random.key(1), 100), partitionable:
    // key_t = threefry2x32((0,1), (0,t))
    uint32_t keys[100][2];
    for (uint32_t t = 0; t < 100; t++)
        h_tf2x32(0u, 1u, 0u, t, keys[t][0], keys[t][1]);

    const uint32_t one = 1u;  // opaque to ptxas: keeps mad.lo as IMAD (fma pipe)

    dim3 grid(GX, GY);  // 16 x 37 = 592 blocks = 148 SMs * 4  (single wave)
    const float* s = bufA;
    float* d = bufB;
    for (int t = 0; t < 99; t++) {
        step_kernel<false><<<grid, 512>>>(s, d, goodp, habp,
                                          keys[t][0], keys[t][1], one);
        const float* tmp = d;
        d = (float*)s;
        s = tmp;
    }
    // Final step: fused * habitat epilogue, writes directly to d_out.
    step_kernel<true><<<grid, 512>>>(s, outp, goodp, habp,
                                     keys[99][0], keys[99][1], one);
}